// round 4
// baseline (speedup 1.0000x reference)
#include <cuda_runtime.h>
#include <cstdint>

// ---------------------------------------------------------------------------
// 2-layer LSTM, S=512, B=64, I=H=1024, fp32 with FFMA2 (fma.rn.f32x2).
//   gemm_bias:       gi = X @ W_ih^T + b_ih + b_hh   (2 launches)
//   lstm_layer:      persistent kernel, 128 CTAs, 512 steps in-kernel,
//                    grid barrier per step, W_hh slice cached in SMEM.
// 4 graph nodes total.
// ---------------------------------------------------------------------------

#define SEQ   512
#define BATCH 64
#define HID   1024
#define G4    4096
#define BH    (BATCH * HID)      // 65536
#define BG    (BATCH * G4)       // 262144
#define YSZ   (SEQ * BH)
#define HOFF  YSZ
#define COFF  (YSZ + 2 * BH)
#define FULL_OUT (YSZ + 4 * BH)
#define NCTA  128

// Scratch (__device__ globals: no allocations allowed)
__device__ __align__(16) float g_gi[SEQ * BG];   // 536 MB input projections
__device__ __align__(16) float g_y0[SEQ * BH];   // 134 MB layer-0 outputs
__device__ int          g_bar_count;             // zero-initialized at load
__device__ volatile int g_bar_gen;

// ---------------- f32x2 helpers -------------------------------------------
__device__ __forceinline__ void ffma2(unsigned long long& acc,
                                      unsigned long long a,
                                      unsigned long long b) {
    asm("fma.rn.f32x2 %0, %1, %2, %0;" : "+l"(acc) : "l"(a), "l"(b));
}
__device__ __forceinline__ unsigned long long dup2(float x) {
    unsigned long long r; unsigned u = __float_as_uint(x);
    asm("mov.b64 %0, {%1, %1};" : "=l"(r) : "r"(u));
    return r;
}
__device__ __forceinline__ float lo32(unsigned long long v) {
    return __uint_as_float((unsigned)v);
}
__device__ __forceinline__ float hi32(unsigned long long v) {
    return __uint_as_float((unsigned)(v >> 32));
}

// ---------------- cp.async helpers ----------------------------------------
__device__ __forceinline__ void cp_async16(unsigned dst, const void* src) {
    asm volatile("cp.async.cg.shared.global [%0], [%1], 16;" :: "r"(dst), "l"(src));
}
__device__ __forceinline__ void cp_commit() {
    asm volatile("cp.async.commit_group;");
}
template <int N> __device__ __forceinline__ void cp_wait() {
    asm volatile("cp.async.wait_group %0;" :: "n"(N));
}

// ---------------- fast activations ----------------------------------------
__device__ __forceinline__ float sigm(float x) {
    return 1.f / (1.f + __expf(-x));
}
__device__ __forceinline__ float tanh_f(float x) {
    // tanh(x) = 1 - 2/(exp(2x)+1)
    return 1.f - 2.f / (__expf(2.f * x) + 1.f);
}

// ---------------------------------------------------------------------------
// C[m][n] = sum_k A[m][k]*W[n][k] + b1[n] + b2[n];  N=4096, K=1024.
// 128x128 tile, 256 threads, 8x8 microtile, FFMA2 paired across n.
__global__ __launch_bounds__(256) void gemm_bias(
    const float* __restrict__ A, const float* __restrict__ W,
    const float* __restrict__ b1, const float* __restrict__ b2,
    float* __restrict__ C)
{
    __shared__ __align__(16) float As[16][132];
    __shared__ __align__(16) float Ws[16][132];
    const int tid = threadIdx.x;
    const int mb = blockIdx.y * 128;
    const int nb = blockIdx.x * 128;
    const int m0 = (tid >> 4) * 8;
    const int n0 = (tid & 15) * 8;

    unsigned long long acc2[8][4];
#pragma unroll
    for (int i = 0; i < 8; i++)
#pragma unroll
        for (int j = 0; j < 4; j++) acc2[i][j] = 0ull;

    for (int kt = 0; kt < 1024; kt += 16) {
#pragma unroll
        for (int t2 = 0; t2 < 2; t2++) {
            int li = tid + t2 * 256;            // [0,512)
            int m  = li >> 2;
            int kq = (li & 3) * 4;
            float4 va = *(const float4*)(A + (size_t)(mb + m) * 1024 + kt + kq);
            As[kq + 0][m] = va.x; As[kq + 1][m] = va.y;
            As[kq + 2][m] = va.z; As[kq + 3][m] = va.w;
            float4 vw = *(const float4*)(W + (size_t)(nb + m) * 1024 + kt + kq);
            Ws[kq + 0][m] = vw.x; Ws[kq + 1][m] = vw.y;
            Ws[kq + 2][m] = vw.z; Ws[kq + 3][m] = vw.w;
        }
        __syncthreads();
#pragma unroll
        for (int k = 0; k < 16; k++) {
            float a[8];
            *(float4*)(a)     = *(const float4*)&As[k][m0];
            *(float4*)(a + 4) = *(const float4*)&As[k][m0 + 4];
            ulonglong2 wq0 = *(const ulonglong2*)&Ws[k][n0];
            ulonglong2 wq1 = *(const ulonglong2*)&Ws[k][n0 + 4];
#pragma unroll
            for (int i = 0; i < 8; i++) {
                unsigned long long ad = dup2(a[i]);
                ffma2(acc2[i][0], ad, wq0.x);
                ffma2(acc2[i][1], ad, wq0.y);
                ffma2(acc2[i][2], ad, wq1.x);
                ffma2(acc2[i][3], ad, wq1.y);
            }
        }
        __syncthreads();
    }

    float bias[8];
#pragma unroll
    for (int j = 0; j < 8; j++) bias[j] = b1[nb + n0 + j] + b2[nb + n0 + j];
#pragma unroll
    for (int i = 0; i < 8; i++) {
        float v[8];
#pragma unroll
        for (int jp = 0; jp < 4; jp++) {
            v[2 * jp]     = lo32(acc2[i][jp]) + bias[2 * jp];
            v[2 * jp + 1] = hi32(acc2[i][jp]) + bias[2 * jp + 1];
        }
        float* cp = C + (size_t)(mb + m0 + i) * 4096 + nb + n0;
        *(float4*)cp       = make_float4(v[0], v[1], v[2], v[3]);
        *(float4*)(cp + 4) = make_float4(v[4], v[5], v[6], v[7]);
    }
}

// ---------------------------------------------------------------------------
// Grid-wide sense barrier (all 128 CTAs resident: 1 CTA/SM, grid <= 148).
__device__ __forceinline__ void grid_sync(int& phase) {
    __syncthreads();
    if (threadIdx.x == 0) {
        __threadfence();
        int old = atomicAdd(&g_bar_count, 1);
        if (old == NCTA - 1) {
            atomicExch(&g_bar_count, 0);
            __threadfence();
            g_bar_gen = phase + 1;
        } else {
            while (g_bar_gen - (phase + 1) < 0) __nanosleep(64);
            __threadfence();
        }
    }
    phase += 1;
    __syncthreads();
}

// ---------------------------------------------------------------------------
// Persistent per-layer LSTM recurrence.
// grid = 128 CTAs x 256 threads. CTA jb owns h-columns [jb*8, jb*8+8),
// i.e. 32 gate columns {g*1024 + jb*8 + jl}. W_hh slice (32x1024) cached in
// SMEM (padded stride 1028). Per step: stage h[t-1] chunks (cp.async, double
// buffered), FFMA2 GEMM paired across k, CTA-local cell update, grid barrier.
//
// SMEM floats: W 32*1028 | Hs 2*64*128 | Gs 32*68 | Cs 512  -> 207872 bytes
#define WSM_N   (32 * 1028)
#define HS_N    (2 * 64 * 128)
#define GS_N    (32 * 68)
#define LSTM_SMEM_FLOATS (WSM_N + HS_N + GS_N + 512)
#define LSTM_SMEM_BYTES  (LSTM_SMEM_FLOATS * 4)

__global__ __launch_bounds__(256) void lstm_layer_kernel(
    const float* __restrict__ Whh, const float* __restrict__ gi,
    float* __restrict__ yout, float* __restrict__ out, int layer, int full)
{
    extern __shared__ __align__(16) float smem[];
    float* Wsm = smem;
    float* Hs  = smem + WSM_N;
    float* Gs  = Hs + HS_N;
    float* Cs  = Gs + GS_N;

    const int tid = threadIdx.x;
    const int jb  = blockIdx.x;                  // 0..127

    // ---- preload W_hh slice into SMEM (once per layer) ----
#pragma unroll 4
    for (int it = 0; it < 32; it++) {
        int idx = tid + it * 256;                // 8192 float4
        int lc  = idx >> 8;                      // local gate col 0..31
        int kq  = (idx & 255) * 4;
        int row = ((lc >> 3) << 10) + jb * 8 + (lc & 7);
        float4 v = *(const float4*)(Whh + (size_t)row * 1024 + kq);
        *(float4*)(Wsm + lc * 1028 + kq) = v;
    }
    for (int i = tid; i < 512; i += 256) Cs[i] = 0.f;
    int bar_phase = g_bar_gen;                   // stable between launches
    __syncthreads();

    const int col = tid & 31;                    // local gate col
    const int b0w = (tid >> 5) * 8;              // 8 batches per thread
    const unsigned hs_u32 =
        (unsigned)__cvta_generic_to_shared(Hs);

    for (int t = 0; t < SEQ; t++) {
        if (t > 0) {
            const float* hprev = yout + (size_t)(t - 1) * BH;
            unsigned long long acc2[8];
#pragma unroll
            for (int i = 0; i < 8; i++) acc2[i] = 0ull;

            // prefetch chunk 0
#pragma unroll
            for (int q = 0; q < 8; q++) {
                int idx = tid + q * 256;
                int b = idx >> 5, kk = (idx & 31) * 4;
                cp_async16(hs_u32 + (unsigned)(b * 128 + kk) * 4,
                           hprev + (size_t)b * HID + kk);
            }
            cp_commit();

            for (int c = 0; c < 8; c++) {
                if (c < 7) {
                    int buf = (c + 1) & 1;
#pragma unroll
                    for (int q = 0; q < 8; q++) {
                        int idx = tid + q * 256;
                        int b = idx >> 5, kk = (idx & 31) * 4;
                        cp_async16(hs_u32 + (unsigned)(buf * 8192 + b * 128 + kk) * 4,
                                   hprev + (size_t)b * HID + (c + 1) * 128 + kk);
                    }
                    cp_commit();
                    cp_wait<1>();
                } else {
                    cp_wait<0>();
                }
                __syncthreads();

                const float* hb = Hs + (c & 1) * 8192;
                const float* wb = Wsm + col * 1028 + c * 128;
#pragma unroll 8
                for (int kk = 0; kk < 128; kk += 4) {
                    ulonglong2 wq = *(const ulonglong2*)(wb + kk);
#pragma unroll
                    for (int i = 0; i < 8; i++) {
                        ulonglong2 hq = *(const ulonglong2*)(hb + (b0w + i) * 128 + kk);
                        ffma2(acc2[i], hq.x, wq.x);
                        ffma2(acc2[i], hq.y, wq.y);
                    }
                }
                __syncthreads();
            }
            // stash gates (recurrent part) into Gs[col][b]
#pragma unroll
            for (int i = 0; i < 8; i++)
                Gs[col * 68 + b0w + i] = lo32(acc2[i]) + hi32(acc2[i]);
            __syncthreads();
        }

        // ---- cell update: 512 cells, 2 per thread (CTA-local) ----
        const float* gi_t = gi + (size_t)t * BG;
        float* hout = yout + (size_t)t * BH;
#pragma unroll
        for (int e = 0; e < 2; e++) {
            int idx = tid * 2 + e;               // 0..511
            int b = idx >> 3;
            int jl = idx & 7;
            int gj = jb * 8 + jl;
            float gv[4];
#pragma unroll
            for (int g = 0; g < 4; g++) {
                float r = (t > 0) ? Gs[(g * 8 + jl) * 68 + b] : 0.f;
                gv[g] = r + gi_t[(size_t)b * 4096 + (g << 10) + gj];
            }
            float si = sigm(gv[0]);
            float sf = sigm(gv[1]);
            float gt = tanh_f(gv[2]);
            float so = sigm(gv[3]);
            float cn = sf * Cs[idx] + si * gt;
            Cs[idx] = cn;
            float h = so * tanh_f(cn);
            hout[(size_t)b * HID + gj] = h;
            if (t == SEQ - 1 && full) {
                out[HOFF + (size_t)layer * BH + (size_t)b * HID + gj] = h;
                out[COFF + (size_t)layer * BH + (size_t)b * HID + gj] = cn;
            }
        }
        if (t < SEQ - 1) grid_sync(bar_phase);
    }
}

// ---------------------------------------------------------------------------
extern "C" void kernel_launch(void* const* d_in, const int* in_sizes, int n_in,
                              void* d_out, int out_size)
{
    const float* x    = (const float*)d_in[0];
    const float* wih0 = (const float*)d_in[1];
    const float* whh0 = (const float*)d_in[2];
    const float* bih0 = (const float*)d_in[3];
    const float* bhh0 = (const float*)d_in[4];
    const float* wih1 = (const float*)d_in[5];
    const float* whh1 = (const float*)d_in[6];
    const float* bih1 = (const float*)d_in[7];
    const float* bhh1 = (const float*)d_in[8];
    float* out = (float*)d_out;

    float *gi, *y0;
    cudaGetSymbolAddress((void**)&gi, g_gi);
    cudaGetSymbolAddress((void**)&y0, g_y0);

    cudaFuncSetAttribute(lstm_layer_kernel,
                         cudaFuncAttributeMaxDynamicSharedMemorySize,
                         LSTM_SMEM_BYTES);

    const int full = (out_size >= FULL_OUT) ? 1 : 0;
    dim3 ggrid(32, 256);                       // N/128 x M/128

    // Layer 0
    gemm_bias<<<ggrid, 256>>>(x, wih0, bih0, bhh0, gi);
    lstm_layer_kernel<<<NCTA, 256, LSTM_SMEM_BYTES>>>(whh0, gi, y0, out, 0, full);
    // Layer 1
    gemm_bias<<<ggrid, 256>>>(y0, wih1, bih1, bhh1, gi);
    lstm_layer_kernel<<<NCTA, 256, LSTM_SMEM_BYTES>>>(whh1, gi, out, out, 1, full);
}

// round 7
// speedup vs baseline: 3.6432x; 3.6432x over previous
#include <cuda_runtime.h>
#include <cuda_fp16.h>
#include <cstdint>

#define SEQ 512
#define BATCH 64
#define HID 1024
#define G4 4096
#define BH (BATCH*HID)
#define BG (BATCH*G4)
#define YSZ (SEQ*BH)
#define HOFF YSZ
#define COFF (YSZ+2*BH)
#define NCTA 128

__device__ __align__(16) float  g_gi[SEQ*BG];    // input projections (fp32)
__device__ __align__(16) __half g_xh[SEQ*BH];    // x in fp16
__device__ __align__(16) __half g_h16[SEQ*BH];   // h stream in fp16 (per layer)
__device__ __align__(16) __half g_wh[G4*HID];    // current layer W_ih fp16
__device__ int g_bar_count;
__device__ volatile int g_bar_gen;

// ---------------- helpers ---------------------------------------------------
__device__ __forceinline__ uint32_t smem_u32(const void* p) {
    uint32_t a;
    asm("{ .reg .u64 t; cvta.to.shared.u64 t, %1; cvt.u32.u64 %0, t; }"
        : "=r"(a) : "l"(p));
    return a;
}
#define SW128(x) ((x) ^ (((x) >> 3) & 0x70))

__device__ __forceinline__ void cp_async16(uint32_t dst, const void* src) {
    asm volatile("cp.async.cg.shared.global [%0], [%1], 16;" :: "r"(dst), "l"(src));
}
__device__ __forceinline__ void cp_commit() {
    asm volatile("cp.async.commit_group;");
}
template <int N> __device__ __forceinline__ void cp_wait() {
    asm volatile("cp.async.wait_group %0;" :: "n"(N));
}
__device__ __forceinline__ void sts128(uint32_t a, uint32_t x, uint32_t y,
                                       uint32_t z, uint32_t w) {
    asm volatile("st.shared.v4.b32 [%0], {%1,%2,%3,%4};"
                 :: "r"(a), "r"(x), "r"(y), "r"(z), "r"(w) : "memory");
}
__device__ __forceinline__ void ldm4(uint32_t* r, uint32_t a) {
    asm volatile("ldmatrix.sync.aligned.m8n8.x4.shared.b16 {%0,%1,%2,%3}, [%4];"
                 : "=r"(r[0]), "=r"(r[1]), "=r"(r[2]), "=r"(r[3]) : "r"(a));
}
__device__ __forceinline__ void ldm2(uint32_t* r, uint32_t a) {
    asm volatile("ldmatrix.sync.aligned.m8n8.x2.shared.b16 {%0,%1}, [%2];"
                 : "=r"(r[0]), "=r"(r[1]) : "r"(a));
}
__device__ __forceinline__ void mma16816(float* c, const uint32_t* a,
                                         const uint32_t* b) {
    asm volatile(
        "mma.sync.aligned.m16n8k16.row.col.f32.f16.f16.f32 "
        "{%0,%1,%2,%3}, {%4,%5,%6,%7}, {%8,%9}, {%0,%1,%2,%3};"
        : "+f"(c[0]), "+f"(c[1]), "+f"(c[2]), "+f"(c[3])
        : "r"(a[0]), "r"(a[1]), "r"(a[2]), "r"(a[3]), "r"(b[0]), "r"(b[1]));
}
__device__ __forceinline__ float sigm(float x)   { return 1.f / (1.f + __expf(-x)); }
__device__ __forceinline__ float tanh_f(float x) { return 1.f - 2.f / (__expf(2.f*x) + 1.f); }
__device__ __forceinline__ uint32_t h2u(__half2 h) { return *(uint32_t*)&h; }

// ---------------------------------------------------------------------------
__global__ void f2h_kernel(const float* __restrict__ in, __half* __restrict__ o,
                           int n8) {
    int i = blockIdx.x * 256 + threadIdx.x;
    if (i < n8) {
        float4 a = ((const float4*)in)[2*i];
        float4 b = ((const float4*)in)[2*i+1];
        uint4 v;
        v.x = h2u(__floats2half2_rn(a.x, a.y));
        v.y = h2u(__floats2half2_rn(a.z, a.w));
        v.z = h2u(__floats2half2_rn(b.x, b.y));
        v.w = h2u(__floats2half2_rn(b.z, b.w));
        ((uint4*)o)[i] = v;
    }
}

// ---------------------------------------------------------------------------
// gi = A(fp16)@B(fp16)^T + b1 + b2.  M=32768,N=4096,K=1024.
// CTA 128x128, 8 warps (2m x 4n), warptile 64x32, k-chunk 64 halfs (128B rows,
// SW128), double-buffered cp.async.
#define GH_SMEM (1024 + 65536)
__global__ __launch_bounds__(256, 2) void gemm_h(
    const __half* __restrict__ A, const __half* __restrict__ B,
    const float* __restrict__ b1, const float* __restrict__ b2,
    float* __restrict__ C)
{
    extern __shared__ char sm_[];
    const uint32_t base = (smem_u32(sm_) + 1023) & ~1023u;
    const int tid = threadIdx.x, wid = tid >> 5, lane = tid & 31;
    const int nb = blockIdx.x * 128, mb = blockIdx.y * 128;
    const int wm = wid >> 2, wn = wid & 3;

    const int lrow = tid >> 1;            // 0..127
    const int ls0  = (tid & 1) * 4;       // seg base 0/4
    const char* asrc0 = (const char*)(A + (size_t)(mb + lrow) * 1024);
    const char* bsrc0 = (const char*)(B + (size_t)(nb + lrow) * 1024);

    float acc[4][4][4];
#pragma unroll
    for (int i = 0; i < 4; i++)
#pragma unroll
        for (int j = 0; j < 4; j++)
#pragma unroll
            for (int q = 0; q < 4; q++) acc[i][j][q] = 0.f;

    const int lr = lane & 7, lg = lane >> 3;
    const int arow = lr + ((lg & 1) << 3), aksel = lg >> 1;
    const int brow = lr + ((lg >> 1) << 3), bksel = lg & 1;

    // prefetch chunk 0
#pragma unroll
    for (int i = 0; i < 4; i++) {
        int s = ls0 + i;
        cp_async16(base + SW128(lrow * 128 + s * 16), asrc0 + s * 16);
        cp_async16(base + 16384 + SW128(lrow * 128 + s * 16), bsrc0 + s * 16);
    }
    cp_commit();

    for (int c = 0; c < 16; c++) {
        if (c < 15) {
            uint32_t ab = base + ((c + 1) & 1) * 32768;
#pragma unroll
            for (int i = 0; i < 4; i++) {
                int s = ls0 + i;
                cp_async16(ab + SW128(lrow * 128 + s * 16),
                           asrc0 + (c + 1) * 128 + s * 16);
                cp_async16(ab + 16384 + SW128(lrow * 128 + s * 16),
                           bsrc0 + (c + 1) * 128 + s * 16);
            }
            cp_commit();
            cp_wait<1>();
        } else {
            cp_wait<0>();
        }
        __syncthreads();
        uint32_t ab = base + (c & 1) * 32768;
        uint32_t bb = ab + 16384;
#pragma unroll
        for (int ks = 0; ks < 4; ks++) {
            uint32_t afr[4][4], bfr[2][4];
#pragma unroll
            for (int mf = 0; mf < 4; mf++)
                ldm4(afr[mf], ab + SW128((wm * 64 + mf * 16 + arow) * 128
                                         + (ks * 2 + aksel) * 16));
#pragma unroll
            for (int bh = 0; bh < 2; bh++)
                ldm4(bfr[bh], bb + SW128((wn * 32 + bh * 16 + brow) * 128
                                         + (ks * 2 + bksel) * 16));
#pragma unroll
            for (int mf = 0; mf < 4; mf++)
#pragma unroll
                for (int nf = 0; nf < 4; nf++)
                    mma16816(acc[mf][nf], afr[mf], &bfr[nf >> 1][(nf & 1) * 2]);
        }
        __syncthreads();
    }

    // epilogue
#pragma unroll
    for (int mf = 0; mf < 4; mf++) {
#pragma unroll
        for (int nf = 0; nf < 4; nf++) {
            int m = mb + wm * 64 + mf * 16 + (lane >> 2);
            int n = nb + wn * 32 + nf * 8 + 2 * (lane & 3);
            float bs0 = b1[n] + b2[n], bs1 = b1[n + 1] + b2[n + 1];
            float* cp0 = C + (size_t)m * 4096 + n;
            float* cp1 = cp0 + 8 * 4096;
            *(float2*)cp0 = make_float2(acc[mf][nf][0] + bs0, acc[mf][nf][1] + bs1);
            *(float2*)cp1 = make_float2(acc[mf][nf][2] + bs0, acc[mf][nf][3] + bs1);
        }
    }
}

// ---------------------------------------------------------------------------
__device__ __forceinline__ void grid_sync(int& phase) {
    __syncthreads();
    if (threadIdx.x == 0) {
        __threadfence();
        int old = atomicAdd(&g_bar_count, 1);
        if (old == NCTA - 1) {
            atomicExch(&g_bar_count, 0);
            __threadfence();
            g_bar_gen = phase + 1;
        } else {
            while (g_bar_gen - (phase + 1) < 0) __nanosleep(32);
            __threadfence();
        }
    }
    phase += 1;
    __syncthreads();
}

// ---------------------------------------------------------------------------
// Persistent recurrence. CTA jb owns 32 gate cols lc=g*8+jl -> row g*1024+jb*8+jl.
// SMEM: W fp16 16 chunks [32lc x 64k] (64KB) | A fp16 16 chunks [64b x 64k]
// (128KB) | Gs fp32 [32][68] (8.7KB).
#define R_SMEM (1024 + 65536 + 131072 + 8704)
__global__ __launch_bounds__(256) void lstm_h(
    const float* __restrict__ Whh, const float* __restrict__ gi,
    __half* __restrict__ h16, float* __restrict__ yout,
    float* __restrict__ out, int layer, int full)
{
    extern __shared__ char sm_[];
    const uint32_t base = (smem_u32(sm_) + 1023) & ~1023u;
    const uint32_t Wb = base, Ab = base + 65536, GsB = base + 196608;
    float* Gs = (float*)(sm_ + (GsB - smem_u32(sm_)));
    const int tid = threadIdx.x, wid = tid >> 5, lane = tid & 31;
    const int jb = blockIdx.x;

    // W_hh slice -> fp16 SMEM
#pragma unroll 2
    for (int it = 0; it < 16; it++) {
        int idx = tid + it * 256;             // 0..4095
        int lc = idx >> 7;                    // 0..31
        int k8 = (idx & 127) * 8;             // 0..1016
        int grow = ((lc >> 3) << 10) + jb * 8 + (lc & 7);
        const float* wp = Whh + (size_t)grow * 1024 + k8;
        float4 u = *(const float4*)wp;
        float4 v = *(const float4*)(wp + 4);
        sts128(Wb + (k8 >> 6) * 4096 + SW128(lc * 128 + (k8 & 63) * 2),
               h2u(__floats2half2_rn(u.x, u.y)), h2u(__floats2half2_rn(u.z, u.w)),
               h2u(__floats2half2_rn(v.x, v.y)), h2u(__floats2half2_rn(v.z, v.w)));
    }
    int bar_phase = g_bar_gen;
    __syncthreads();

    const int wm = wid >> 2, wn = wid & 3;    // m-half, gate
    const int m0 = wm * 32, n0 = wn * 8;
    const int lr = lane & 7, lg = lane >> 3;
    const int arow = lr + ((lg & 1) << 3), aksel = lg >> 1;
    const int brow = lane & 15;               // x2: lanes 0..15 meaningful
    const int bksel = (brow >> 3) & 1, bnr = brow & 7;

    const int ldrow = tid >> 3;               // 0..31 (+32)
    const int lds   = tid & 7;

    float creg[8];
#pragma unroll
    for (int i = 0; i < 8; i++) creg[i] = 0.f;

    for (int t = 0; t < SEQ; t++) {
        if (t > 0) {
            const char* hp = (const char*)(h16 + (size_t)(t - 1) * BH);
            // stage full h (64x1024 fp16) into 16 chunks
#pragma unroll 4
            for (int c = 0; c < 16; c++) {
                cp_async16(Ab + c * 8192 + SW128(ldrow * 128 + lds * 16),
                           hp + ldrow * 2048 + c * 128 + lds * 16);
                cp_async16(Ab + c * 8192 + SW128((ldrow + 32) * 128 + lds * 16),
                           hp + (ldrow + 32) * 2048 + c * 128 + lds * 16);
            }
            cp_commit();
            cp_wait<0>();
            __syncthreads();

            float acc[2][4];
#pragma unroll
            for (int f = 0; f < 2; f++)
#pragma unroll
                for (int q = 0; q < 4; q++) acc[f][q] = 0.f;

            for (int c = 0; c < 16; c++) {
#pragma unroll
                for (int ks = 0; ks < 4; ks++) {
                    uint32_t afr[2][4], bfr[2];
                    ldm4(afr[0], Ab + c * 8192
                         + SW128((m0 + arow) * 128 + (ks * 2 + aksel) * 16));
                    ldm4(afr[1], Ab + c * 8192
                         + SW128((m0 + 16 + arow) * 128 + (ks * 2 + aksel) * 16));
                    ldm2(bfr, Wb + c * 4096
                         + SW128((n0 + bnr) * 128 + (ks * 2 + bksel) * 16));
                    mma16816(acc[0], afr[0], bfr);
                    mma16816(acc[1], afr[1], bfr);
                }
            }
            // exchange gates via SMEM: Gs[col][b]
#pragma unroll
            for (int f = 0; f < 2; f++) {
                int b = m0 + f * 16 + (lane >> 2);
                int col = n0 + 2 * (lane & 3);
                Gs[col * 68 + b]           = acc[f][0];
                Gs[(col + 1) * 68 + b]     = acc[f][1];
                Gs[col * 68 + b + 8]       = acc[f][2];
                Gs[(col + 1) * 68 + b + 8] = acc[f][3];
            }
            __syncthreads();
        }

        // ---- cell update: warps 0-1, one batch row per thread ----
        if (wid < 2) {
            int b = wid * 32 + lane;
            const float* gp = gi + (size_t)t * BG + (size_t)b * 4096 + jb * 8;
            float gg[4][8];
#pragma unroll
            for (int g = 0; g < 4; g++) {
                *(float4*)&gg[g][0] = *(const float4*)(gp + (g << 10));
                *(float4*)&gg[g][4] = *(const float4*)(gp + (g << 10) + 4);
            }
            float hv[8];
#pragma unroll
            for (int jl = 0; jl < 8; jl++) {
                float i_g = gg[0][jl], f_g = gg[1][jl];
                float g_g = gg[2][jl], o_g = gg[3][jl];
                if (t > 0) {
                    i_g += Gs[(0 * 8 + jl) * 68 + b];
                    f_g += Gs[(1 * 8 + jl) * 68 + b];
                    g_g += Gs[(2 * 8 + jl) * 68 + b];
                    o_g += Gs[(3 * 8 + jl) * 68 + b];
                }
                float cn = sigm(f_g) * creg[jl] + sigm(i_g) * tanh_f(g_g);
                creg[jl] = cn;
                hv[jl] = sigm(o_g) * tanh_f(cn);
            }
            // fp16 h stream (recurrence + next-layer GEMM operand)
            uint4 hp16;
            hp16.x = h2u(__floats2half2_rn(hv[0], hv[1]));
            hp16.y = h2u(__floats2half2_rn(hv[2], hv[3]));
            hp16.z = h2u(__floats2half2_rn(hv[4], hv[5]));
            hp16.w = h2u(__floats2half2_rn(hv[6], hv[7]));
            *(uint4*)(h16 + (size_t)t * BH + (size_t)b * 1024 + jb * 8) = hp16;
            if (yout) {
                float* yq = yout + (size_t)t * BH + (size_t)b * 1024 + jb * 8;
                *(float4*)yq       = make_float4(hv[0], hv[1], hv[2], hv[3]);
                *(float4*)(yq + 4) = make_float4(hv[4], hv[5], hv[6], hv[7]);
            }
            if (t == SEQ - 1 && full) {
                float* ho = out + HOFF + (size_t)layer * BH + (size_t)b * 1024 + jb * 8;
                float* co = out + COFF + (size_t)layer * BH + (size_t)b * 1024 + jb * 8;
                *(float4*)ho       = make_float4(hv[0], hv[1], hv[2], hv[3]);
                *(float4*)(ho + 4) = make_float4(hv[4], hv[5], hv[6], hv[7]);
                *(float4*)co       = make_float4(creg[0], creg[1], creg[2], creg[3]);
                *(float4*)(co + 4) = make_float4(creg[4], creg[5], creg[6], creg[7]);
            }
        }
        if (t < SEQ - 1) grid_sync(bar_phase);
    }
}

// ---------------------------------------------------------------------------
extern "C" void kernel_launch(void* const* d_in, const int* in_sizes, int n_in,
                              void* d_out, int out_size)
{
    const float* x    = (const float*)d_in[0];
    const float* wih0 = (const float*)d_in[1];
    const float* whh0 = (const float*)d_in[2];
    const float* bih0 = (const float*)d_in[3];
    const float* bhh0 = (const float*)d_in[4];
    const float* wih1 = (const float*)d_in[5];
    const float* whh1 = (const float*)d_in[6];
    const float* bih1 = (const float*)d_in[7];
    const float* bhh1 = (const float*)d_in[8];
    float* out = (float*)d_out;

    float *gi; __half *xh, *h16, *wh;
    cudaGetSymbolAddress((void**)&gi,  g_gi);
    cudaGetSymbolAddress((void**)&xh,  g_xh);
    cudaGetSymbolAddress((void**)&h16, g_h16);
    cudaGetSymbolAddress((void**)&wh,  g_wh);

    cudaFuncSetAttribute(gemm_h, cudaFuncAttributeMaxDynamicSharedMemorySize, GH_SMEM);
    cudaFuncSetAttribute(lstm_h, cudaFuncAttributeMaxDynamicSharedMemorySize, R_SMEM);

    const int full = (out_size >= (int)(YSZ + 4 * BH)) ? 1 : 0;
    dim3 gg(32, 256);

    // Layer 0
    f2h_kernel<<<(SEQ * BH / 8 + 255) / 256, 256>>>(x, xh, SEQ * BH / 8);
    f2h_kernel<<<(G4 * HID / 8 + 255) / 256, 256>>>(wih0, wh, G4 * HID / 8);
    gemm_h<<<gg, 256, GH_SMEM>>>(xh, wh, bih0, bhh0, gi);
    lstm_h<<<NCTA, 256, R_SMEM>>>(whh0, gi, h16, (float*)0, out, 0, full);
    // Layer 1 (A operand = h16 written by layer 0)
    f2h_kernel<<<(G4 * HID / 8 + 255) / 256, 256>>>(wih1, wh, G4 * HID / 8);
    gemm_h<<<gg, 256, GH_SMEM>>>(h16, wh, bih1, bhh1, gi);
    lstm_h<<<NCTA, 256, R_SMEM>>>(whh1, gi, h16, out, out, 1, full);
}